// round 7
// baseline (speedup 1.0000x reference)
#include <cuda_runtime.h>

// TrajectoryGeneratorAR_goal: S=256 rollouts x N=64 agents, OBS=8 encoder LSTM
// steps, PRED=12 autoregressive decoder steps with pairwise pooling net.
// Round 7: 512 threads per CTA (4 warps/SMSP at occ 1 -> double the latency
// coverage R3-R6 lacked), pooling tile-1 with direct smem-atomic flush so the
// live set fits the 128-reg budget WITHOUT spilling (R5's failure mode).
// LSTM phases use 8 threads/agent (2 gate units each).

namespace {

constexpr int S_BATCH  = 256;
constexpr int NAG      = 64;
constexpr int BTOT     = S_BATCH * NAG;   // 16384
constexpr int OBS      = 8;
constexpr int PRED     = 12;
constexpr int H        = 16;
constexpr int NTHREADS = 512;
constexpr int MAXPAIRS = NAG * NAG;

struct __align__(16) Smem {
    float h[NAG][17];
    float c[NAG][17];
    float ctx[NAG][17];
    float hjp[NAG][65];
    float curr[NAG][2];
    float outp[NAG][2];
    float goal[NAG][2];
    unsigned long long nmask[NAG];
    int   pfx[NAG + 1];
    unsigned short plist[MAXPAIRS];    // (i<<6)|j, sorted by i
    alignas(16) float embW[32];
    alignas(16) float embB[16];
    alignas(16) float encWih[16*64];
    alignas(16) float encWhh[16*64];
    alignas(16) float encB[64];
    alignas(16) float decinW[18*16];
    alignas(16) float decinB[16];
    alignas(16) float decWih[16*64];
    alignas(16) float decWhh[16*64];
    alignas(16) float decB[64];
    alignas(16) float peW[32];
    alignas(16) float peB[16];
    alignas(16) float W1pT[64*16];   // [k][d]  (pool_W1 rows 0..15, transposed)
    alignas(16) float W1h [16*64];   // [d][k]  (pool_W1 rows 16..31)
    alignas(16) float b1  [64];
    alignas(16) float W2  [64*16];   // [k][u]
    alignas(16) float b2  [16];
    alignas(16) float h2p1W[18*16];
    alignas(16) float h2p1B[16];
    alignas(16) float h2p2W[16*4];
    alignas(16) float h2p2B[4];
};

__device__ __forceinline__ float sigm(float x)   { return 1.0f / (1.0f + __expf(-x)); }
__device__ __forceinline__ float tanh_f(float x) { return 2.0f / (1.0f + __expf(-2.0f * x)) - 1.0f; }

__device__ __forceinline__ void cpw(float* dst, const float* src, int n, int tid) {
    for (int k = tid; k < n; k += NTHREADS) dst[k] = src[k];
}

} // namespace

__global__ __launch_bounds__(NTHREADS, 1)
void traj_ar_kernel(
    const float* __restrict__ traj_rel,
    const float* __restrict__ obs_pos,
    const float* __restrict__ goal_g,
    const float* __restrict__ embW, const float* __restrict__ embB,
    const float* __restrict__ encWih, const float* __restrict__ encWhh, const float* __restrict__ encB,
    const float* __restrict__ decinW, const float* __restrict__ decinB,
    const float* __restrict__ decWih, const float* __restrict__ decWhh, const float* __restrict__ decB,
    const float* __restrict__ peW, const float* __restrict__ peB,
    const float* __restrict__ W1, const float* __restrict__ b1,
    const float* __restrict__ W2, const float* __restrict__ b2,
    const float* __restrict__ h2p1W, const float* __restrict__ h2p1B,
    const float* __restrict__ h2p2W, const float* __restrict__ h2p2B,
    const int* __restrict__ nei,
    float* __restrict__ out, int out_size)
{
    extern __shared__ unsigned char smem_raw[];
    Smem& sm = *reinterpret_cast<Smem*>(smem_raw);
    const int tid = threadIdx.x;
    const int s   = blockIdx.x;

    if (s == 0 && tid == 0) {
        for (int idx = PRED * BTOT * 2; idx < out_size; ++idx) out[idx] = 0.0f;
    }

    // ---------------- weight staging + state init ----------------
    cpw(sm.embW,  embW,  32,  tid);  cpw(sm.embB,  embB,  16, tid);
    cpw(sm.encWih, encWih, 1024, tid); cpw(sm.encWhh, encWhh, 1024, tid); cpw(sm.encB, encB, 64, tid);
    cpw(sm.decinW, decinW, 288, tid);  cpw(sm.decinB, decinB, 16, tid);
    cpw(sm.decWih, decWih, 1024, tid); cpw(sm.decWhh, decWhh, 1024, tid); cpw(sm.decB, decB, 64, tid);
    cpw(sm.peW, peW, 32, tid); cpw(sm.peB, peB, 16, tid);
    for (int idx = tid; idx < 1024; idx += NTHREADS) {
        const int k = idx >> 4, d = idx & 15;
        sm.W1pT[idx] = W1[d * 64 + k];
    }
    cpw(sm.W1h, W1 + 1024, 1024, tid);
    cpw(sm.b1, b1, 64, tid); cpw(sm.W2, W2, 1024, tid); cpw(sm.b2, b2, 16, tid);
    cpw(sm.h2p1W, h2p1W, 288, tid); cpw(sm.h2p1B, h2p1B, 16, tid);
    cpw(sm.h2p2W, h2p2W, 64, tid);  cpw(sm.h2p2B, h2p2B, 4, tid);

    for (int idx = tid; idx < NAG * 17; idx += NTHREADS) {
        (&sm.h[0][0])[idx] = 0.0f; (&sm.c[0][0])[idx] = 0.0f; (&sm.ctx[0][0])[idx] = 0.0f;
    }
    if (tid < NAG) {
        sm.nmask[tid] = 0ull;
        const int b = s * NAG + tid;
        const float c0 = obs_pos[((OBS - 1) * BTOT + b) * 2 + 0];
        const float c1 = obs_pos[((OBS - 1) * BTOT + b) * 2 + 1];
        sm.curr[tid][0] = c0; sm.curr[tid][1] = c1;
        sm.outp[tid][0] = traj_rel[((OBS - 1) * BTOT + b) * 2 + 0];
        sm.outp[tid][1] = traj_rel[((OBS - 1) * BTOT + b) * 2 + 1];
        sm.goal[tid][0] = goal_g[b * 2 + 0] - c0;
        sm.goal[tid][1] = goal_g[b * 2 + 1] - c1;
    }
    __syncthreads();
    {
        const int base = s * (NAG * NAG);
        #pragma unroll
        for (int r = 0; r < (NAG * NAG) / NTHREADS; ++r) {
            const int flat = r * NTHREADS + tid;
            if (nei[base + flat] != 0)
                atomicOr(&sm.nmask[flat >> 6], 1ull << (flat & 63));
        }
    }
    __syncthreads();
    // ---- compacted (i,j) pair list, sorted by i (mask static over steps) ----
    if (tid == 0) {
        int run = 0;
        #pragma unroll
        for (int i = 0; i < NAG; ++i) { sm.pfx[i] = run; run += __popcll(sm.nmask[i]); }
        sm.pfx[NAG] = run;
    }
    __syncthreads();
    if (tid < NAG) {
        unsigned long long m = sm.nmask[tid];
        int w = sm.pfx[tid];
        const unsigned short ibase = (unsigned short)(tid << 6);
        while (m) {
            const int j = __ffsll((long long)m) - 1;
            m &= m - 1;
            sm.plist[w++] = (unsigned short)(ibase | j);
        }
    }
    __syncthreads();
    const int P       = sm.pfx[NAG];
    const int pbase   = P >> 9;                 // P / 512
    const int prem    = P & (NTHREADS - 1);
    const int mystart = tid * pbase + (tid < prem ? tid : prem);
    const int mycnt   = pbase + (tid < prem ? 1 : 0);

    const int a   = tid >> 3;   // agent owned by this oct (8 threads/agent)
    const int sub = tid & 7;    // oct lane: owns hidden units [sub*2, sub*2+2)

    // ---------------- history encoder ----------------
    for (int t = 0; t < OBS; ++t) {
        const int b = s * NAG + a;
        const float x0 = traj_rel[(t * BTOT + b) * 2 + 0];
        const float x1 = traj_rel[(t * BTOT + b) * 2 + 1];
        float emb[H];
        #pragma unroll
        for (int u = 0; u < H; ++u)
            emb[u] = fmaxf(fmaf(x0, sm.embW[u], fmaf(x1, sm.embW[16 + u], sm.embB[u])), 0.0f);
        float hold[H];
        #pragma unroll
        for (int d = 0; d < H; ++d) hold[d] = sm.h[a][d];
        float hn[2], cn[2];
        #pragma unroll
        for (int q = 0; q < 2; ++q) {
            const int u = sub * 2 + q;
            float gi = sm.encB[u], gf = sm.encB[16 + u], gg = sm.encB[32 + u], go = sm.encB[48 + u];
            #pragma unroll
            for (int d = 0; d < H; ++d) {
                const float e = emb[d], hd = hold[d];
                gi = fmaf(e, sm.encWih[d * 64 + u],        gi); gi = fmaf(hd, sm.encWhh[d * 64 + u],        gi);
                gf = fmaf(e, sm.encWih[d * 64 + 16 + u],   gf); gf = fmaf(hd, sm.encWhh[d * 64 + 16 + u],   gf);
                gg = fmaf(e, sm.encWih[d * 64 + 32 + u],   gg); gg = fmaf(hd, sm.encWhh[d * 64 + 32 + u],   gg);
                go = fmaf(e, sm.encWih[d * 64 + 48 + u],   go); go = fmaf(hd, sm.encWhh[d * 64 + 48 + u],   go);
            }
            const float cN = sigm(gf) * sm.c[a][u] + sigm(gi) * tanh_f(gg);
            cn[q] = cN; hn[q] = sigm(go) * tanh_f(cN);
        }
        __syncwarp();   // 8-thread agent groups live inside one warp
        #pragma unroll
        for (int q = 0; q < 2; ++q) { sm.h[a][sub * 2 + q] = hn[q]; sm.c[a][sub * 2 + q] = cn[q]; }
        __syncwarp();
    }
    #pragma unroll
    for (int q = 0; q < 2; ++q) sm.c[a][sub * 2 + q] = 0.0f;
    __syncthreads();

    // ---------------- autoregressive decoder ----------------
    for (int step = 0; step < PRED; ++step) {
        // decoder input embed + LSTM (oct per agent, 2 gate units/thread)
        float ctxv[H];
        #pragma unroll
        for (int d = 0; d < H; ++d) ctxv[d] = sm.ctx[a][d];
        const float o0 = sm.outp[a][0], o1 = sm.outp[a][1];
        float emb[H];
        #pragma unroll
        for (int u = 0; u < H; ++u) {
            float acc = sm.decinB[u];
            #pragma unroll
            for (int d = 0; d < H; ++d) acc = fmaf(ctxv[d], sm.decinW[d * 16 + u], acc);
            acc = fmaf(o0, sm.decinW[256 + u], fmaf(o1, sm.decinW[272 + u], acc));
            emb[u] = fmaxf(acc, 0.0f);
        }
        float hold[H];
        #pragma unroll
        for (int d = 0; d < H; ++d) hold[d] = sm.h[a][d];
        float hn[2], cn[2];
        #pragma unroll
        for (int q = 0; q < 2; ++q) {
            const int u = sub * 2 + q;
            float gi = sm.decB[u], gf = sm.decB[16 + u], gg = sm.decB[32 + u], go = sm.decB[48 + u];
            #pragma unroll
            for (int d = 0; d < H; ++d) {
                const float e = emb[d], hd = hold[d];
                gi = fmaf(e, sm.decWih[d * 64 + u],        gi); gi = fmaf(hd, sm.decWhh[d * 64 + u],        gi);
                gf = fmaf(e, sm.decWih[d * 64 + 16 + u],   gf); gf = fmaf(hd, sm.decWhh[d * 64 + 16 + u],   gf);
                gg = fmaf(e, sm.decWih[d * 64 + 32 + u],   gg); gg = fmaf(hd, sm.decWhh[d * 64 + 32 + u],   gg);
                go = fmaf(e, sm.decWih[d * 64 + 48 + u],   go); go = fmaf(hd, sm.decWhh[d * 64 + 48 + u],   go);
            }
            const float cN = sigm(gf) * sm.c[a][u] + sigm(gi) * tanh_f(gg);
            cn[q] = cN; hn[q] = sigm(go) * tanh_f(cN);
        }
        __syncthreads();
        #pragma unroll
        for (int q = 0; q < 2; ++q) { sm.h[a][sub * 2 + q] = hn[q]; sm.c[a][sub * 2 + q] = cn[q]; }
        __syncthreads();

        // hjp[j][k] = h_j . W1h[:,k] + b1[k]   (8 k's per thread)
        {
            const int j = a, k0 = sub * 8;
            float hv[H];
            #pragma unroll
            for (int d = 0; d < H; ++d) hv[d] = sm.h[j][d];
            #pragma unroll
            for (int kk = 0; kk < 8; ++kk) {
                const int k = k0 + kk;
                float acc = sm.b1[k];
                #pragma unroll
                for (int d = 0; d < H; ++d) acc = fmaf(hv[d], sm.W1h[d * 64 + k], acc);
                sm.hjp[j][k] = acc;
            }
        }
        for (int idx = tid; idx < NAG * 17; idx += NTHREADS) (&sm.ctx[0][0])[idx] = 0.0f;
        __syncthreads();

        // ---- pooling: tile-1 per thread, direct atomic flush (low reg use) ----
        for (int t = 0; t < mycnt; ++t) {
            const int pr = sm.plist[mystart + t];
            const int i = pr >> 6, j = pr & 63;
            const float dx = sm.curr[i][0] - sm.curr[j][0];
            const float dy = sm.curr[i][1] - sm.curr[j][1];
            float pe[H], m[H];
            #pragma unroll
            for (int u = 0; u < H; ++u) {
                pe[u] = fmaxf(fmaf(dx, sm.peW[u], fmaf(dy, sm.peW[16 + u], sm.peB[u])), 0.0f);
                m[u]  = 0.0f;
            }
            const float* __restrict__ hjrow = sm.hjp[j];
            for (int k = 0; k < 64; ++k) {
                const float4* w1q = reinterpret_cast<const float4*>(sm.W1pT + (k << 4));
                const float4 wa = w1q[0], wb = w1q[1], wc = w1q[2], wd = w1q[3];
                // two independent half-chains
                float aA = hjrow[k], aB = 0.0f;
                aA = fmaf(pe[0],  wa.x, aA); aB = fmaf(pe[8],  wc.x, aB);
                aA = fmaf(pe[1],  wa.y, aA); aB = fmaf(pe[9],  wc.y, aB);
                aA = fmaf(pe[2],  wa.z, aA); aB = fmaf(pe[10], wc.z, aB);
                aA = fmaf(pe[3],  wa.w, aA); aB = fmaf(pe[11], wc.w, aB);
                aA = fmaf(pe[4],  wb.x, aA); aB = fmaf(pe[12], wd.x, aB);
                aA = fmaf(pe[5],  wb.y, aA); aB = fmaf(pe[13], wd.y, aB);
                aA = fmaf(pe[6],  wb.z, aA); aB = fmaf(pe[14], wd.z, aB);
                aA = fmaf(pe[7],  wb.w, aA); aB = fmaf(pe[15], wd.w, aB);
                const float av = fmaxf(aA + aB, 0.0f);
                const float4* w2q = reinterpret_cast<const float4*>(sm.W2 + (k << 4));
                const float4 va = w2q[0], vb = w2q[1], vc = w2q[2], vd = w2q[3];
                m[0]  = fmaf(av, va.x, m[0]);  m[1]  = fmaf(av, va.y, m[1]);
                m[2]  = fmaf(av, va.z, m[2]);  m[3]  = fmaf(av, va.w, m[3]);
                m[4]  = fmaf(av, vb.x, m[4]);  m[5]  = fmaf(av, vb.y, m[5]);
                m[6]  = fmaf(av, vb.z, m[6]);  m[7]  = fmaf(av, vb.w, m[7]);
                m[8]  = fmaf(av, vc.x, m[8]);  m[9]  = fmaf(av, vc.y, m[9]);
                m[10] = fmaf(av, vc.z, m[10]); m[11] = fmaf(av, vc.w, m[11]);
                m[12] = fmaf(av, vd.x, m[12]); m[13] = fmaf(av, vd.y, m[13]);
                m[14] = fmaf(av, vd.z, m[14]); m[15] = fmaf(av, vd.w, m[15]);
            }
            #pragma unroll
            for (int u = 0; u < H; ++u)
                atomicAdd(&sm.ctx[i][u], fmaxf(m[u] + sm.b2[u], 0.0f));
        }
        __syncthreads();

        // output head (one thread per agent)
        if (tid < NAG) {
            float hv[H], hh[H];
            #pragma unroll
            for (int u = 0; u < H; ++u) hv[u] = sm.h[tid][u] + sm.ctx[tid][u];
            const float g0 = sm.goal[tid][0], g1 = sm.goal[tid][1];
            #pragma unroll
            for (int u = 0; u < H; ++u) {
                float acc = sm.h2p1B[u];
                #pragma unroll
                for (int d = 0; d < H; ++d) acc = fmaf(hv[d], sm.h2p1W[d * 16 + u], acc);
                acc = fmaf(g0, sm.h2p1W[256 + u], fmaf(g1, sm.h2p1W[272 + u], acc));
                hh[u] = fmaxf(acc, 0.0f);
            }
            float mu0 = sm.h2p2B[0], mu1 = sm.h2p2B[1];
            #pragma unroll
            for (int d = 0; d < H; ++d) {
                mu0 = fmaf(hh[d], sm.h2p2W[d * 4 + 0], mu0);
                mu1 = fmaf(hh[d], sm.h2p2W[d * 4 + 1], mu1);
            }
            const int b = s * NAG + tid;
            out[(step * BTOT + b) * 2 + 0] = mu0;
            out[(step * BTOT + b) * 2 + 1] = mu1;
            sm.outp[tid][0] = mu0; sm.outp[tid][1] = mu1;
            sm.curr[tid][0] += mu0; sm.curr[tid][1] += mu1;
        }
        __syncthreads();
    }
}

extern "C" void kernel_launch(void* const* d_in, const int* in_sizes, int n_in,
                              void* d_out, int out_size)
{
    (void)in_sizes; (void)n_in;
    cudaFuncSetAttribute(traj_ar_kernel, cudaFuncAttributeMaxDynamicSharedMemorySize,
                         (int)sizeof(Smem));
    traj_ar_kernel<<<S_BATCH, NTHREADS, sizeof(Smem)>>>(
        (const float*)d_in[0],
        (const float*)d_in[1],
        (const float*)d_in[2],
        (const float*)d_in[4],  (const float*)d_in[5],
        (const float*)d_in[6],  (const float*)d_in[7],  (const float*)d_in[8],
        (const float*)d_in[9],  (const float*)d_in[10],
        (const float*)d_in[11], (const float*)d_in[12], (const float*)d_in[13],
        (const float*)d_in[14], (const float*)d_in[15],
        (const float*)d_in[16], (const float*)d_in[17],
        (const float*)d_in[18], (const float*)d_in[19],
        (const float*)d_in[20], (const float*)d_in[21],
        (const float*)d_in[22], (const float*)d_in[23],
        (const int*)d_in[24],
        (float*)d_out, out_size);
}

// round 8
// speedup vs baseline: 1.2906x; 1.2906x over previous
#include <cuda_runtime.h>

// TrajectoryGeneratorAR_goal: S=256 rollouts x N=64 agents, OBS=8 encoder LSTM
// steps, PRED=12 autoregressive decoder steps with pairwise pooling net.
// One CTA per rollout, 256 threads, smem-resident.
// Round 8: pooling keeps the compacted pair list (half work) but the per-k
// indirect scalar load hjp[j][k] — the stall every sparse variant shared —
// is removed: each pair's hjp row is preloaded into registers in float4
// chunks, and the k-loop body is pure FFMA + warp-uniform weight loads.

namespace {

constexpr int S_BATCH  = 256;
constexpr int NAG      = 64;
constexpr int BTOT     = S_BATCH * NAG;   // 16384
constexpr int OBS      = 8;
constexpr int PRED     = 12;
constexpr int H        = 16;
constexpr int NTHREADS = 256;
constexpr int MAXPAIRS = NAG * NAG;
constexpr int HJSTRIDE = 68;              // 16B-aligned rows for float4 loads

struct __align__(16) Smem {
    float h[NAG][17];
    float c[NAG][17];
    float ctx[NAG][17];
    alignas(16) float hjp[NAG][HJSTRIDE];
    float curr[NAG][2];
    float outp[NAG][2];
    float goal[NAG][2];
    unsigned long long nmask[NAG];
    int   pfx[NAG + 1];
    unsigned short plist[MAXPAIRS];    // (i<<6)|j, sorted by i
    alignas(16) float embW[32];
    alignas(16) float embB[16];
    alignas(16) float encWih[16*64];
    alignas(16) float encWhh[16*64];
    alignas(16) float encB[64];
    alignas(16) float decinW[18*16];
    alignas(16) float decinB[16];
    alignas(16) float decWih[16*64];
    alignas(16) float decWhh[16*64];
    alignas(16) float decB[64];
    alignas(16) float peW[32];
    alignas(16) float peB[16];
    alignas(16) float W1pT[64*16];   // [k][d]  (pool_W1 rows 0..15, transposed)
    alignas(16) float W1h [16*64];   // [d][k]  (pool_W1 rows 16..31)
    alignas(16) float b1  [64];
    alignas(16) float W2  [64*16];   // [k][u]
    alignas(16) float b2  [16];
    alignas(16) float h2p1W[18*16];
    alignas(16) float h2p1B[16];
    alignas(16) float h2p2W[16*4];
    alignas(16) float h2p2B[4];
};

__device__ __forceinline__ float sigm(float x)   { return 1.0f / (1.0f + __expf(-x)); }
__device__ __forceinline__ float tanh_f(float x) { return 2.0f / (1.0f + __expf(-2.0f * x)) - 1.0f; }

__device__ __forceinline__ void cpw(float* dst, const float* src, int n, int tid) {
    for (int k = tid; k < n; k += NTHREADS) dst[k] = src[k];
}

} // namespace

__global__ __launch_bounds__(NTHREADS)
void traj_ar_kernel(
    const float* __restrict__ traj_rel,
    const float* __restrict__ obs_pos,
    const float* __restrict__ goal_g,
    const float* __restrict__ embW, const float* __restrict__ embB,
    const float* __restrict__ encWih, const float* __restrict__ encWhh, const float* __restrict__ encB,
    const float* __restrict__ decinW, const float* __restrict__ decinB,
    const float* __restrict__ decWih, const float* __restrict__ decWhh, const float* __restrict__ decB,
    const float* __restrict__ peW, const float* __restrict__ peB,
    const float* __restrict__ W1, const float* __restrict__ b1,
    const float* __restrict__ W2, const float* __restrict__ b2,
    const float* __restrict__ h2p1W, const float* __restrict__ h2p1B,
    const float* __restrict__ h2p2W, const float* __restrict__ h2p2B,
    const int* __restrict__ nei,
    float* __restrict__ out, int out_size)
{
    extern __shared__ unsigned char smem_raw[];
    Smem& sm = *reinterpret_cast<Smem*>(smem_raw);
    const int tid = threadIdx.x;
    const int s   = blockIdx.x;

    if (s == 0 && tid == 0) {
        for (int idx = PRED * BTOT * 2; idx < out_size; ++idx) out[idx] = 0.0f;
    }

    // ---------------- weight staging + state init ----------------
    cpw(sm.embW,  embW,  32,  tid);  cpw(sm.embB,  embB,  16, tid);
    cpw(sm.encWih, encWih, 1024, tid); cpw(sm.encWhh, encWhh, 1024, tid); cpw(sm.encB, encB, 64, tid);
    cpw(sm.decinW, decinW, 288, tid);  cpw(sm.decinB, decinB, 16, tid);
    cpw(sm.decWih, decWih, 1024, tid); cpw(sm.decWhh, decWhh, 1024, tid); cpw(sm.decB, decB, 64, tid);
    cpw(sm.peW, peW, 32, tid); cpw(sm.peB, peB, 16, tid);
    for (int idx = tid; idx < 1024; idx += NTHREADS) {
        const int k = idx >> 4, d = idx & 15;
        sm.W1pT[idx] = W1[d * 64 + k];
    }
    cpw(sm.W1h, W1 + 1024, 1024, tid);
    cpw(sm.b1, b1, 64, tid); cpw(sm.W2, W2, 1024, tid); cpw(sm.b2, b2, 16, tid);
    cpw(sm.h2p1W, h2p1W, 288, tid); cpw(sm.h2p1B, h2p1B, 16, tid);
    cpw(sm.h2p2W, h2p2W, 64, tid);  cpw(sm.h2p2B, h2p2B, 4, tid);

    for (int idx = tid; idx < NAG * 17; idx += NTHREADS) {
        (&sm.h[0][0])[idx] = 0.0f; (&sm.c[0][0])[idx] = 0.0f; (&sm.ctx[0][0])[idx] = 0.0f;
    }
    if (tid < NAG) {
        sm.nmask[tid] = 0ull;
        const int b = s * NAG + tid;
        const float c0 = obs_pos[((OBS - 1) * BTOT + b) * 2 + 0];
        const float c1 = obs_pos[((OBS - 1) * BTOT + b) * 2 + 1];
        sm.curr[tid][0] = c0; sm.curr[tid][1] = c1;
        sm.outp[tid][0] = traj_rel[((OBS - 1) * BTOT + b) * 2 + 0];
        sm.outp[tid][1] = traj_rel[((OBS - 1) * BTOT + b) * 2 + 1];
        sm.goal[tid][0] = goal_g[b * 2 + 0] - c0;
        sm.goal[tid][1] = goal_g[b * 2 + 1] - c1;
    }
    __syncthreads();
    {
        const int base = s * (NAG * NAG);
        #pragma unroll
        for (int r = 0; r < (NAG * NAG) / NTHREADS; ++r) {
            const int flat = r * NTHREADS + tid;
            if (nei[base + flat] != 0)
                atomicOr(&sm.nmask[flat >> 6], 1ull << (flat & 63));
        }
    }
    __syncthreads();
    // ---- compacted (i,j) pair list, sorted by i (mask static over steps) ----
    if (tid == 0) {
        int run = 0;
        #pragma unroll
        for (int i = 0; i < NAG; ++i) { sm.pfx[i] = run; run += __popcll(sm.nmask[i]); }
        sm.pfx[NAG] = run;
    }
    __syncthreads();
    if (tid < NAG) {
        unsigned long long m = sm.nmask[tid];
        int w = sm.pfx[tid];
        const unsigned short ibase = (unsigned short)(tid << 6);
        while (m) {
            const int j = __ffsll((long long)m) - 1;
            m &= m - 1;
            sm.plist[w++] = (unsigned short)(ibase | j);
        }
    }
    __syncthreads();
    const int P       = sm.pfx[NAG];
    const int pbase   = P >> 8;
    const int prem    = P & (NTHREADS - 1);
    const int mystart = tid * pbase + (tid < prem ? tid : prem);
    const int mycnt   = pbase + (tid < prem ? 1 : 0);

    const int a   = tid >> 2;
    const int sub = tid & 3;

    // ---------------- history encoder ----------------
    for (int t = 0; t < OBS; ++t) {
        const int b = s * NAG + a;
        const float x0 = traj_rel[(t * BTOT + b) * 2 + 0];
        const float x1 = traj_rel[(t * BTOT + b) * 2 + 1];
        float emb[H];
        #pragma unroll
        for (int u = 0; u < H; ++u)
            emb[u] = fmaxf(fmaf(x0, sm.embW[u], fmaf(x1, sm.embW[16 + u], sm.embB[u])), 0.0f);
        float hold[H];
        #pragma unroll
        for (int d = 0; d < H; ++d) hold[d] = sm.h[a][d];
        float hn[4], cn[4];
        #pragma unroll
        for (int q = 0; q < 4; ++q) {
            const int u = sub * 4 + q;
            float gi = sm.encB[u], gf = sm.encB[16 + u], gg = sm.encB[32 + u], go = sm.encB[48 + u];
            #pragma unroll
            for (int d = 0; d < H; ++d) {
                const float e = emb[d], hd = hold[d];
                gi = fmaf(e, sm.encWih[d * 64 + u],        gi); gi = fmaf(hd, sm.encWhh[d * 64 + u],        gi);
                gf = fmaf(e, sm.encWih[d * 64 + 16 + u],   gf); gf = fmaf(hd, sm.encWhh[d * 64 + 16 + u],   gf);
                gg = fmaf(e, sm.encWih[d * 64 + 32 + u],   gg); gg = fmaf(hd, sm.encWhh[d * 64 + 32 + u],   gg);
                go = fmaf(e, sm.encWih[d * 64 + 48 + u],   go); go = fmaf(hd, sm.encWhh[d * 64 + 48 + u],   go);
            }
            const float cN = sigm(gf) * sm.c[a][u] + sigm(gi) * tanh_f(gg);
            cn[q] = cN; hn[q] = sigm(go) * tanh_f(cN);
        }
        __syncwarp();
        #pragma unroll
        for (int q = 0; q < 4; ++q) { sm.h[a][sub * 4 + q] = hn[q]; sm.c[a][sub * 4 + q] = cn[q]; }
        __syncwarp();
    }
    #pragma unroll
    for (int q = 0; q < 4; ++q) sm.c[a][sub * 4 + q] = 0.0f;
    __syncthreads();

    // ---------------- autoregressive decoder ----------------
    for (int step = 0; step < PRED; ++step) {
        // decoder input embed + LSTM (quad per agent)
        float ctxv[H];
        #pragma unroll
        for (int d = 0; d < H; ++d) ctxv[d] = sm.ctx[a][d];
        const float o0 = sm.outp[a][0], o1 = sm.outp[a][1];
        float emb[H];
        #pragma unroll
        for (int u = 0; u < H; ++u) {
            float acc = sm.decinB[u];
            #pragma unroll
            for (int d = 0; d < H; ++d) acc = fmaf(ctxv[d], sm.decinW[d * 16 + u], acc);
            acc = fmaf(o0, sm.decinW[256 + u], fmaf(o1, sm.decinW[272 + u], acc));
            emb[u] = fmaxf(acc, 0.0f);
        }
        float hold[H];
        #pragma unroll
        for (int d = 0; d < H; ++d) hold[d] = sm.h[a][d];
        float hn[4], cn[4];
        #pragma unroll
        for (int q = 0; q < 4; ++q) {
            const int u = sub * 4 + q;
            float gi = sm.decB[u], gf = sm.decB[16 + u], gg = sm.decB[32 + u], go = sm.decB[48 + u];
            #pragma unroll
            for (int d = 0; d < H; ++d) {
                const float e = emb[d], hd = hold[d];
                gi = fmaf(e, sm.decWih[d * 64 + u],        gi); gi = fmaf(hd, sm.decWhh[d * 64 + u],        gi);
                gf = fmaf(e, sm.decWih[d * 64 + 16 + u],   gf); gf = fmaf(hd, sm.decWhh[d * 64 + 16 + u],   gf);
                gg = fmaf(e, sm.decWih[d * 64 + 32 + u],   gg); gg = fmaf(hd, sm.decWhh[d * 64 + 32 + u],   gg);
                go = fmaf(e, sm.decWih[d * 64 + 48 + u],   go); go = fmaf(hd, sm.decWhh[d * 64 + 48 + u],   go);
            }
            const float cN = sigm(gf) * sm.c[a][u] + sigm(gi) * tanh_f(gg);
            cn[q] = cN; hn[q] = sigm(go) * tanh_f(cN);
        }
        __syncthreads();
        #pragma unroll
        for (int q = 0; q < 4; ++q) { sm.h[a][sub * 4 + q] = hn[q]; sm.c[a][sub * 4 + q] = cn[q]; }
        __syncthreads();

        // hjp[j][k] = h_j . W1h[:,k] + b1[k]; zero ctx accumulators
        {
            const int j = a, k0 = sub * 16;
            float hv[H];
            #pragma unroll
            for (int d = 0; d < H; ++d) hv[d] = sm.h[j][d];
            #pragma unroll
            for (int kk = 0; kk < 16; ++kk) {
                const int k = k0 + kk;
                float acc = sm.b1[k];
                #pragma unroll
                for (int d = 0; d < H; ++d) acc = fmaf(hv[d], sm.W1h[d * 64 + k], acc);
                sm.hjp[j][k] = acc;
            }
        }
        for (int idx = tid; idx < NAG * 17; idx += NTHREADS) (&sm.ctx[0][0])[idx] = 0.0f;
        __syncthreads();

        // ---- pooling: tile-1, hjp row preloaded to registers in chunks ----
        {
            int   cur_i = -1;
            float acc[H];
            for (int t = 0; t < mycnt; ++t) {
                const int pr = sm.plist[mystart + t];
                const int i = pr >> 6, j = pr & 63;
                const float dx = sm.curr[i][0] - sm.curr[j][0];
                const float dy = sm.curr[i][1] - sm.curr[j][1];
                float pe[H], m[H];
                #pragma unroll
                for (int u = 0; u < H; ++u) {
                    pe[u] = fmaxf(fmaf(dx, sm.peW[u], fmaf(dy, sm.peW[16 + u], sm.peB[u])), 0.0f);
                    m[u]  = 0.0f;
                }
                const float4* __restrict__ hj4 = reinterpret_cast<const float4*>(sm.hjp[j]);
                for (int kc = 0; kc < 8; ++kc) {
                    // 8 hjp values for this chunk -> registers (compile-time indexed below)
                    const float4 hA = hj4[kc * 2], hB = hj4[kc * 2 + 1];
                    const float hjc[8] = { hA.x, hA.y, hA.z, hA.w, hB.x, hB.y, hB.z, hB.w };
                    #pragma unroll
                    for (int kk = 0; kk < 8; ++kk) {
                        const int k = kc * 8 + kk;
                        const float4* w1q = reinterpret_cast<const float4*>(sm.W1pT + (k << 4));
                        const float4 wa = w1q[0], wb = w1q[1], wc = w1q[2], wd = w1q[3];
                        float aA = hjc[kk], aB = 0.0f;   // two independent half-chains
                        aA = fmaf(pe[0],  wa.x, aA); aB = fmaf(pe[8],  wc.x, aB);
                        aA = fmaf(pe[1],  wa.y, aA); aB = fmaf(pe[9],  wc.y, aB);
                        aA = fmaf(pe[2],  wa.z, aA); aB = fmaf(pe[10], wc.z, aB);
                        aA = fmaf(pe[3],  wa.w, aA); aB = fmaf(pe[11], wc.w, aB);
                        aA = fmaf(pe[4],  wb.x, aA); aB = fmaf(pe[12], wd.x, aB);
                        aA = fmaf(pe[5],  wb.y, aA); aB = fmaf(pe[13], wd.y, aB);
                        aA = fmaf(pe[6],  wb.z, aA); aB = fmaf(pe[14], wd.z, aB);
                        aA = fmaf(pe[7],  wb.w, aA); aB = fmaf(pe[15], wd.w, aB);
                        const float av = fmaxf(aA + aB, 0.0f);
                        const float4* w2q = reinterpret_cast<const float4*>(sm.W2 + (k << 4));
                        const float4 va = w2q[0], vb = w2q[1], vc = w2q[2], vd = w2q[3];
                        m[0]  = fmaf(av, va.x, m[0]);  m[1]  = fmaf(av, va.y, m[1]);
                        m[2]  = fmaf(av, va.z, m[2]);  m[3]  = fmaf(av, va.w, m[3]);
                        m[4]  = fmaf(av, vb.x, m[4]);  m[5]  = fmaf(av, vb.y, m[5]);
                        m[6]  = fmaf(av, vb.z, m[6]);  m[7]  = fmaf(av, vb.w, m[7]);
                        m[8]  = fmaf(av, vc.x, m[8]);  m[9]  = fmaf(av, vc.y, m[9]);
                        m[10] = fmaf(av, vc.z, m[10]); m[11] = fmaf(av, vc.w, m[11]);
                        m[12] = fmaf(av, vd.x, m[12]); m[13] = fmaf(av, vd.y, m[13]);
                        m[14] = fmaf(av, vd.z, m[14]); m[15] = fmaf(av, vd.w, m[15]);
                    }
                }
                if (i == cur_i) {
                    #pragma unroll
                    for (int u = 0; u < H; ++u) acc[u] += fmaxf(m[u] + sm.b2[u], 0.0f);
                } else {
                    if (cur_i >= 0) {
                        #pragma unroll
                        for (int u = 0; u < H; ++u) atomicAdd(&sm.ctx[cur_i][u], acc[u]);
                    }
                    cur_i = i;
                    #pragma unroll
                    for (int u = 0; u < H; ++u) acc[u] = fmaxf(m[u] + sm.b2[u], 0.0f);
                }
            }
            if (cur_i >= 0) {
                #pragma unroll
                for (int u = 0; u < H; ++u) atomicAdd(&sm.ctx[cur_i][u], acc[u]);
            }
        }
        __syncthreads();

        // output head (one thread per agent)
        if (tid < NAG) {
            float hv[H], hh[H];
            #pragma unroll
            for (int u = 0; u < H; ++u) hv[u] = sm.h[tid][u] + sm.ctx[tid][u];
            const float g0 = sm.goal[tid][0], g1 = sm.goal[tid][1];
            #pragma unroll
            for (int u = 0; u < H; ++u) {
                float acc = sm.h2p1B[u];
                #pragma unroll
                for (int d = 0; d < H; ++d) acc = fmaf(hv[d], sm.h2p1W[d * 16 + u], acc);
                acc = fmaf(g0, sm.h2p1W[256 + u], fmaf(g1, sm.h2p1W[272 + u], acc));
                hh[u] = fmaxf(acc, 0.0f);
            }
            float mu0 = sm.h2p2B[0], mu1 = sm.h2p2B[1];
            #pragma unroll
            for (int d = 0; d < H; ++d) {
                mu0 = fmaf(hh[d], sm.h2p2W[d * 4 + 0], mu0);
                mu1 = fmaf(hh[d], sm.h2p2W[d * 4 + 1], mu1);
            }
            const int b = s * NAG + tid;
            out[(step * BTOT + b) * 2 + 0] = mu0;
            out[(step * BTOT + b) * 2 + 1] = mu1;
            sm.outp[tid][0] = mu0; sm.outp[tid][1] = mu1;
            sm.curr[tid][0] += mu0; sm.curr[tid][1] += mu1;
        }
        __syncthreads();
    }
}

extern "C" void kernel_launch(void* const* d_in, const int* in_sizes, int n_in,
                              void* d_out, int out_size)
{
    (void)in_sizes; (void)n_in;
    cudaFuncSetAttribute(traj_ar_kernel, cudaFuncAttributeMaxDynamicSharedMemorySize,
                         (int)sizeof(Smem));
    traj_ar_kernel<<<S_BATCH, NTHREADS, sizeof(Smem)>>>(
        (const float*)d_in[0],
        (const float*)d_in[1],
        (const float*)d_in[2],
        (const float*)d_in[4],  (const float*)d_in[5],
        (const float*)d_in[6],  (const float*)d_in[7],  (const float*)d_in[8],
        (const float*)d_in[9],  (const float*)d_in[10],
        (const float*)d_in[11], (const float*)d_in[12], (const float*)d_in[13],
        (const float*)d_in[14], (const float*)d_in[15],
        (const float*)d_in[16], (const float*)d_in[17],
        (const float*)d_in[18], (const float*)d_in[19],
        (const float*)d_in[20], (const float*)d_in[21],
        (const float*)d_in[22], (const float*)d_in[23],
        (const int*)d_in[24],
        (float*)d_out, out_size);
}

// round 10
// speedup vs baseline: 1.3271x; 1.0283x over previous
#include <cuda_runtime.h>

// TrajectoryGeneratorAR_goal: S=256 rollouts x N=64 agents, OBS=8 encoder LSTM
// steps, PRED=12 autoregressive decoder steps with pairwise pooling net.
// Round 10 = Round 9 resubmitted (R9 hit a broker-side container failure;
// bench never ran). 128 CTAs x 512 threads, TWO samples per CTA: single wave
// (128 <= 148 SMs), 4 warps/SMSP latency coverage, compacted pair list
// across both samples, tile-1 pool + register segment accumulator epilogue.

namespace {

constexpr int S_BATCH  = 256;
constexpr int NAG      = 64;     // agents per sample
constexpr int NAGC     = 128;    // agents per CTA (2 samples)
constexpr int BTOT     = S_BATCH * NAG;   // 16384
constexpr int OBS      = 8;
constexpr int PRED     = 12;
constexpr int H        = 16;
constexpr int NTHREADS = 512;
constexpr int NCTAS    = S_BATCH / 2;     // 128
constexpr int MAXPAIRS = NAGC * NAG;      // 8192

struct __align__(16) Smem {
    float h[NAGC][17];
    float c[NAGC][17];
    float ctx[NAGC][17];
    float hjp[NAGC][65];
    float curr[NAGC][2];
    float outp[NAGC][2];
    float goal[NAGC][2];
    unsigned long long nmask[NAGC];   // bit j(local): neighbor mask row i(global)
    int   pfx[NAGC + 1];
    unsigned short plist[MAXPAIRS];   // (i<<7)|j_global, sorted by i
    alignas(16) float embW[32];
    alignas(16) float embB[16];
    alignas(16) float encWih[16*64];
    alignas(16) float encWhh[16*64];
    alignas(16) float encB[64];
    alignas(16) float decinW[18*16];
    alignas(16) float decinB[16];
    alignas(16) float decWih[16*64];
    alignas(16) float decWhh[16*64];
    alignas(16) float decB[64];
    alignas(16) float peW[32];
    alignas(16) float peB[16];
    alignas(16) float W1pT[64*16];   // [k][d]  (pool_W1 rows 0..15, transposed)
    alignas(16) float W1h [16*64];   // [d][k]  (pool_W1 rows 16..31)
    alignas(16) float b1  [64];
    alignas(16) float W2  [64*16];   // [k][u]
    alignas(16) float b2  [16];
    alignas(16) float h2p1W[18*16];
    alignas(16) float h2p1B[16];
    alignas(16) float h2p2W[16*4];
    alignas(16) float h2p2B[4];
};

__device__ __forceinline__ float sigm(float x)   { return 1.0f / (1.0f + __expf(-x)); }
__device__ __forceinline__ float tanh_f(float x) { return 2.0f / (1.0f + __expf(-2.0f * x)) - 1.0f; }

__device__ __forceinline__ void cpw(float* dst, const float* src, int n, int tid) {
    for (int k = tid; k < n; k += NTHREADS) dst[k] = src[k];
}

} // namespace

__global__ __launch_bounds__(NTHREADS, 1)
void traj_ar_kernel(
    const float* __restrict__ traj_rel,
    const float* __restrict__ obs_pos,
    const float* __restrict__ goal_g,
    const float* __restrict__ embW, const float* __restrict__ embB,
    const float* __restrict__ encWih, const float* __restrict__ encWhh, const float* __restrict__ encB,
    const float* __restrict__ decinW, const float* __restrict__ decinB,
    const float* __restrict__ decWih, const float* __restrict__ decWhh, const float* __restrict__ decB,
    const float* __restrict__ peW, const float* __restrict__ peB,
    const float* __restrict__ W1, const float* __restrict__ b1,
    const float* __restrict__ W2, const float* __restrict__ b2,
    const float* __restrict__ h2p1W, const float* __restrict__ h2p1B,
    const float* __restrict__ h2p2W, const float* __restrict__ h2p2B,
    const int* __restrict__ nei,
    float* __restrict__ out, int out_size)
{
    extern __shared__ unsigned char smem_raw[];
    Smem& sm = *reinterpret_cast<Smem*>(smem_raw);
    const int tid = threadIdx.x;
    const int sb  = blockIdx.x;           // CTA handles samples 2sb, 2sb+1
    const int gb  = sb * NAGC;            // global batch base for this CTA

    if (sb == 0 && tid == 0) {
        for (int idx = PRED * BTOT * 2; idx < out_size; ++idx) out[idx] = 0.0f;
    }

    // ---------------- weight staging + state init ----------------
    cpw(sm.embW,  embW,  32,  tid);  cpw(sm.embB,  embB,  16, tid);
    cpw(sm.encWih, encWih, 1024, tid); cpw(sm.encWhh, encWhh, 1024, tid); cpw(sm.encB, encB, 64, tid);
    cpw(sm.decinW, decinW, 288, tid);  cpw(sm.decinB, decinB, 16, tid);
    cpw(sm.decWih, decWih, 1024, tid); cpw(sm.decWhh, decWhh, 1024, tid); cpw(sm.decB, decB, 64, tid);
    cpw(sm.peW, peW, 32, tid); cpw(sm.peB, peB, 16, tid);
    for (int idx = tid; idx < 1024; idx += NTHREADS) {
        const int k = idx >> 4, d = idx & 15;
        sm.W1pT[idx] = W1[d * 64 + k];
    }
    cpw(sm.W1h, W1 + 1024, 1024, tid);
    cpw(sm.b1, b1, 64, tid); cpw(sm.W2, W2, 1024, tid); cpw(sm.b2, b2, 16, tid);
    cpw(sm.h2p1W, h2p1W, 288, tid); cpw(sm.h2p1B, h2p1B, 16, tid);
    cpw(sm.h2p2W, h2p2W, 64, tid);  cpw(sm.h2p2B, h2p2B, 4, tid);

    for (int idx = tid; idx < NAGC * 17; idx += NTHREADS) {
        (&sm.h[0][0])[idx] = 0.0f; (&sm.c[0][0])[idx] = 0.0f; (&sm.ctx[0][0])[idx] = 0.0f;
    }
    if (tid < NAGC) {
        sm.nmask[tid] = 0ull;
        const int b = gb + tid;
        const float c0 = obs_pos[((OBS - 1) * BTOT + b) * 2 + 0];
        const float c1 = obs_pos[((OBS - 1) * BTOT + b) * 2 + 1];
        sm.curr[tid][0] = c0; sm.curr[tid][1] = c1;
        sm.outp[tid][0] = traj_rel[((OBS - 1) * BTOT + b) * 2 + 0];
        sm.outp[tid][1] = traj_rel[((OBS - 1) * BTOT + b) * 2 + 1];
        sm.goal[tid][0] = goal_g[b * 2 + 0] - c0;
        sm.goal[tid][1] = goal_g[b * 2 + 1] - c1;
    }
    __syncthreads();
    {   // neighbor masks for both samples: row i' (0..127), local j (0..63)
        const int base = gb * NAG;
        #pragma unroll
        for (int r = 0; r < (NAGC * NAG) / NTHREADS; ++r) {
            const int flat = r * NTHREADS + tid;          // i'*64 + j
            if (nei[base + flat] != 0)
                atomicOr(&sm.nmask[flat >> 6], 1ull << (flat & 63));
        }
    }
    __syncthreads();
    // ---- compacted (i, j_global) pair list, sorted by i ----
    if (tid == 0) {
        int run = 0;
        for (int i = 0; i < NAGC; ++i) { sm.pfx[i] = run; run += __popcll(sm.nmask[i]); }
        sm.pfx[NAGC] = run;
    }
    __syncthreads();
    if (tid < NAGC) {
        unsigned long long m = sm.nmask[tid];
        int w = sm.pfx[tid];
        const int jbase = tid & 64;                // sample offset for j
        const unsigned short ibase = (unsigned short)(tid << 7);
        while (m) {
            const int j = __ffsll((long long)m) - 1;
            m &= m - 1;
            sm.plist[w++] = (unsigned short)(ibase | (unsigned short)(jbase + j));
        }
    }
    __syncthreads();
    const int P       = sm.pfx[NAGC];
    const int pbase   = P >> 9;                    // P / 512
    const int prem    = P & (NTHREADS - 1);
    const int mystart = tid * pbase + (tid < prem ? tid : prem);
    const int mycnt   = pbase + (tid < prem ? 1 : 0);

    const int a   = tid >> 2;   // agent 0..127 (both samples)
    const int sub = tid & 3;

    // ---------------- history encoder ----------------
    for (int t = 0; t < OBS; ++t) {
        const int b = gb + a;
        const float x0 = traj_rel[(t * BTOT + b) * 2 + 0];
        const float x1 = traj_rel[(t * BTOT + b) * 2 + 1];
        float emb[H];
        #pragma unroll
        for (int u = 0; u < H; ++u)
            emb[u] = fmaxf(fmaf(x0, sm.embW[u], fmaf(x1, sm.embW[16 + u], sm.embB[u])), 0.0f);
        float hold[H];
        #pragma unroll
        for (int d = 0; d < H; ++d) hold[d] = sm.h[a][d];
        float hn[4], cn[4];
        #pragma unroll
        for (int q = 0; q < 4; ++q) {
            const int u = sub * 4 + q;
            float gi = sm.encB[u], gf = sm.encB[16 + u], gg = sm.encB[32 + u], go = sm.encB[48 + u];
            #pragma unroll
            for (int d = 0; d < H; ++d) {
                const float e = emb[d], hd = hold[d];
                gi = fmaf(e, sm.encWih[d * 64 + u],        gi); gi = fmaf(hd, sm.encWhh[d * 64 + u],        gi);
                gf = fmaf(e, sm.encWih[d * 64 + 16 + u],   gf); gf = fmaf(hd, sm.encWhh[d * 64 + 16 + u],   gf);
                gg = fmaf(e, sm.encWih[d * 64 + 32 + u],   gg); gg = fmaf(hd, sm.encWhh[d * 64 + 32 + u],   gg);
                go = fmaf(e, sm.encWih[d * 64 + 48 + u],   go); go = fmaf(hd, sm.encWhh[d * 64 + 48 + u],   go);
            }
            const float cN = sigm(gf) * sm.c[a][u] + sigm(gi) * tanh_f(gg);
            cn[q] = cN; hn[q] = sigm(go) * tanh_f(cN);
        }
        __syncwarp();   // quads live inside one warp
        #pragma unroll
        for (int q = 0; q < 4; ++q) { sm.h[a][sub * 4 + q] = hn[q]; sm.c[a][sub * 4 + q] = cn[q]; }
        __syncwarp();
    }
    #pragma unroll
    for (int q = 0; q < 4; ++q) sm.c[a][sub * 4 + q] = 0.0f;
    __syncthreads();

    // ---------------- autoregressive decoder ----------------
    for (int step = 0; step < PRED; ++step) {
        // decoder input embed + LSTM (quad per agent)
        float ctxv[H];
        #pragma unroll
        for (int d = 0; d < H; ++d) ctxv[d] = sm.ctx[a][d];
        const float o0 = sm.outp[a][0], o1 = sm.outp[a][1];
        float emb[H];
        #pragma unroll
        for (int u = 0; u < H; ++u) {
            float acc = sm.decinB[u];
            #pragma unroll
            for (int d = 0; d < H; ++d) acc = fmaf(ctxv[d], sm.decinW[d * 16 + u], acc);
            acc = fmaf(o0, sm.decinW[256 + u], fmaf(o1, sm.decinW[272 + u], acc));
            emb[u] = fmaxf(acc, 0.0f);
        }
        float hold[H];
        #pragma unroll
        for (int d = 0; d < H; ++d) hold[d] = sm.h[a][d];
        float hn[4], cn[4];
        #pragma unroll
        for (int q = 0; q < 4; ++q) {
            const int u = sub * 4 + q;
            float gi = sm.decB[u], gf = sm.decB[16 + u], gg = sm.decB[32 + u], go = sm.decB[48 + u];
            #pragma unroll
            for (int d = 0; d < H; ++d) {
                const float e = emb[d], hd = hold[d];
                gi = fmaf(e, sm.decWih[d * 64 + u],        gi); gi = fmaf(hd, sm.decWhh[d * 64 + u],        gi);
                gf = fmaf(e, sm.decWih[d * 64 + 16 + u],   gf); gf = fmaf(hd, sm.decWhh[d * 64 + 16 + u],   gf);
                gg = fmaf(e, sm.decWih[d * 64 + 32 + u],   gg); gg = fmaf(hd, sm.decWhh[d * 64 + 32 + u],   gg);
                go = fmaf(e, sm.decWih[d * 64 + 48 + u],   go); go = fmaf(hd, sm.decWhh[d * 64 + 48 + u],   go);
            }
            const float cN = sigm(gf) * sm.c[a][u] + sigm(gi) * tanh_f(gg);
            cn[q] = cN; hn[q] = sigm(go) * tanh_f(cN);
        }
        __syncthreads();
        #pragma unroll
        for (int q = 0; q < 4; ++q) { sm.h[a][sub * 4 + q] = hn[q]; sm.c[a][sub * 4 + q] = cn[q]; }
        __syncthreads();

        // hjp[j][k] = h_j . W1h[:,k] + b1[k]; zero ctx accumulators
        {
            const int j = a, k0 = sub * 16;
            float hv[H];
            #pragma unroll
            for (int d = 0; d < H; ++d) hv[d] = sm.h[j][d];
            #pragma unroll
            for (int kk = 0; kk < 16; ++kk) {
                const int k = k0 + kk;
                float acc = sm.b1[k];
                #pragma unroll
                for (int d = 0; d < H; ++d) acc = fmaf(hv[d], sm.W1h[d * 64 + k], acc);
                sm.hjp[j][k] = acc;
            }
        }
        for (int idx = tid; idx < NAGC * 17; idx += NTHREADS) (&sm.ctx[0][0])[idx] = 0.0f;
        __syncthreads();

        // ---- pooling over pair list: tile-1, register segment accumulator ----
        {
            int   cur_i = -1;
            float acc[H];
            for (int t = 0; t < mycnt; ++t) {
                const int pr = sm.plist[mystart + t];
                const int i = pr >> 7, j = pr & 127;
                const float dx = sm.curr[i][0] - sm.curr[j][0];
                const float dy = sm.curr[i][1] - sm.curr[j][1];
                float pe[H], m[H];
                #pragma unroll
                for (int u = 0; u < H; ++u) {
                    pe[u] = fmaxf(fmaf(dx, sm.peW[u], fmaf(dy, sm.peW[16 + u], sm.peB[u])), 0.0f);
                    m[u]  = 0.0f;
                }
                const float* __restrict__ hjrow = sm.hjp[j];
                for (int k = 0; k < 64; ++k) {
                    const float4* w1q = reinterpret_cast<const float4*>(sm.W1pT + (k << 4));
                    const float4 wa = w1q[0], wb = w1q[1], wc = w1q[2], wd = w1q[3];
                    float aA = hjrow[k], aB = 0.0f;   // two independent half-chains
                    aA = fmaf(pe[0],  wa.x, aA); aB = fmaf(pe[8],  wc.x, aB);
                    aA = fmaf(pe[1],  wa.y, aA); aB = fmaf(pe[9],  wc.y, aB);
                    aA = fmaf(pe[2],  wa.z, aA); aB = fmaf(pe[10], wc.z, aB);
                    aA = fmaf(pe[3],  wa.w, aA); aB = fmaf(pe[11], wc.w, aB);
                    aA = fmaf(pe[4],  wb.x, aA); aB = fmaf(pe[12], wd.x, aB);
                    aA = fmaf(pe[5],  wb.y, aA); aB = fmaf(pe[13], wd.y, aB);
                    aA = fmaf(pe[6],  wb.z, aA); aB = fmaf(pe[14], wd.z, aB);
                    aA = fmaf(pe[7],  wb.w, aA); aB = fmaf(pe[15], wd.w, aB);
                    const float av = fmaxf(aA + aB, 0.0f);
                    const float4* w2q = reinterpret_cast<const float4*>(sm.W2 + (k << 4));
                    const float4 va = w2q[0], vb = w2q[1], vc = w2q[2], vd = w2q[3];
                    m[0]  = fmaf(av, va.x, m[0]);  m[1]  = fmaf(av, va.y, m[1]);
                    m[2]  = fmaf(av, va.z, m[2]);  m[3]  = fmaf(av, va.w, m[3]);
                    m[4]  = fmaf(av, vb.x, m[4]);  m[5]  = fmaf(av, vb.y, m[5]);
                    m[6]  = fmaf(av, vb.z, m[6]);  m[7]  = fmaf(av, vb.w, m[7]);
                    m[8]  = fmaf(av, vc.x, m[8]);  m[9]  = fmaf(av, vc.y, m[9]);
                    m[10] = fmaf(av, vc.z, m[10]); m[11] = fmaf(av, vc.w, m[11]);
                    m[12] = fmaf(av, vd.x, m[12]); m[13] = fmaf(av, vd.y, m[13]);
                    m[14] = fmaf(av, vd.z, m[14]); m[15] = fmaf(av, vd.w, m[15]);
                }
                if (i == cur_i) {
                    #pragma unroll
                    for (int u = 0; u < H; ++u) acc[u] += fmaxf(m[u] + sm.b2[u], 0.0f);
                } else {
                    if (cur_i >= 0) {
                        #pragma unroll
                        for (int u = 0; u < H; ++u) atomicAdd(&sm.ctx[cur_i][u], acc[u]);
                    }
                    cur_i = i;
                    #pragma unroll
                    for (int u = 0; u < H; ++u) acc[u] = fmaxf(m[u] + sm.b2[u], 0.0f);
                }
            }
            if (cur_i >= 0) {
                #pragma unroll
                for (int u = 0; u < H; ++u) atomicAdd(&sm.ctx[cur_i][u], acc[u]);
            }
        }
        __syncthreads();

        // output head (one thread per agent, both samples)
        if (tid < NAGC) {
            float hv[H], hh[H];
            #pragma unroll
            for (int u = 0; u < H; ++u) hv[u] = sm.h[tid][u] + sm.ctx[tid][u];
            const float g0 = sm.goal[tid][0], g1 = sm.goal[tid][1];
            #pragma unroll
            for (int u = 0; u < H; ++u) {
                float acc = sm.h2p1B[u];
                #pragma unroll
                for (int d = 0; d < H; ++d) acc = fmaf(hv[d], sm.h2p1W[d * 16 + u], acc);
                acc = fmaf(g0, sm.h2p1W[256 + u], fmaf(g1, sm.h2p1W[272 + u], acc));
                hh[u] = fmaxf(acc, 0.0f);
            }
            float mu0 = sm.h2p2B[0], mu1 = sm.h2p2B[1];
            #pragma unroll
            for (int d = 0; d < H; ++d) {
                mu0 = fmaf(hh[d], sm.h2p2W[d * 4 + 0], mu0);
                mu1 = fmaf(hh[d], sm.h2p2W[d * 4 + 1], mu1);
            }
            const int b = gb + tid;
            out[(step * BTOT + b) * 2 + 0] = mu0;
            out[(step * BTOT + b) * 2 + 1] = mu1;
            sm.outp[tid][0] = mu0; sm.outp[tid][1] = mu1;
            sm.curr[tid][0] += mu0; sm.curr[tid][1] += mu1;
        }
        __syncthreads();
    }
}

extern "C" void kernel_launch(void* const* d_in, const int* in_sizes, int n_in,
                              void* d_out, int out_size)
{
    (void)in_sizes; (void)n_in;
    cudaFuncSetAttribute(traj_ar_kernel, cudaFuncAttributeMaxDynamicSharedMemorySize,
                         (int)sizeof(Smem));
    traj_ar_kernel<<<NCTAS, NTHREADS, sizeof(Smem)>>>(
        (const float*)d_in[0],
        (const float*)d_in[1],
        (const float*)d_in[2],
        (const float*)d_in[4],  (const float*)d_in[5],
        (const float*)d_in[6],  (const float*)d_in[7],  (const float*)d_in[8],
        (const float*)d_in[9],  (const float*)d_in[10],
        (const float*)d_in[11], (const float*)d_in[12], (const float*)d_in[13],
        (const float*)d_in[14], (const float*)d_in[15],
        (const float*)d_in[16], (const float*)d_in[17],
        (const float*)d_in[18], (const float*)d_in[19],
        (const float*)d_in[20], (const float*)d_in[21],
        (const float*)d_in[22], (const float*)d_in[23],
        (const int*)d_in[24],
        (float*)d_out, out_size);
}

// round 11
// speedup vs baseline: 1.3491x; 1.0165x over previous
#include <cuda_runtime.h>

// TrajectoryGeneratorAR_goal: S=256 rollouts x N=64 agents, OBS=8 encoder LSTM
// steps, PRED=12 autoregressive decoder steps with pairwise pooling net.
// Round 11: 128 CTAs x 384 threads, 2 samples/CTA. Single wave (<=148 SMs)
// AND 3 warps/SMSP at a 168-reg budget — between R6 (2 warps, 255 regs, no
// spill, latency-bound) and R10 (4 warps, 128 regs, spilled). LSTM/hjp use
// 2 threads/agent; pooling balanced over all 384 threads.

namespace {

constexpr int S_BATCH  = 256;
constexpr int NAG      = 64;     // agents per sample
constexpr int NAGC     = 128;    // agents per CTA (2 samples)
constexpr int BTOT     = S_BATCH * NAG;   // 16384
constexpr int OBS      = 8;
constexpr int PRED     = 12;
constexpr int H        = 16;
constexpr int NTHREADS = 384;
constexpr int NCTAS    = S_BATCH / 2;     // 128
constexpr int MAXPAIRS = NAGC * NAG;      // 8192

struct __align__(16) Smem {
    float h[NAGC][17];
    float c[NAGC][17];
    float ctx[NAGC][17];
    float hjp[NAGC][65];
    float curr[NAGC][2];
    float outp[NAGC][2];
    float goal[NAGC][2];
    unsigned long long nmask[NAGC];
    int   pfx[NAGC + 1];
    unsigned short plist[MAXPAIRS];   // (i<<7)|j, sorted by i
    alignas(16) float embW[32];
    alignas(16) float embB[16];
    alignas(16) float encWih[16*64];
    alignas(16) float encWhh[16*64];
    alignas(16) float encB[64];
    alignas(16) float decinW[18*16];
    alignas(16) float decinB[16];
    alignas(16) float decWih[16*64];
    alignas(16) float decWhh[16*64];
    alignas(16) float decB[64];
    alignas(16) float peW[32];
    alignas(16) float peB[16];
    alignas(16) float W1pT[64*16];   // [k][d]  (pool_W1 rows 0..15, transposed)
    alignas(16) float W1h [16*64];   // [d][k]  (pool_W1 rows 16..31)
    alignas(16) float b1  [64];
    alignas(16) float W2  [64*16];   // [k][u]
    alignas(16) float b2  [16];
    alignas(16) float h2p1W[18*16];
    alignas(16) float h2p1B[16];
    alignas(16) float h2p2W[16*4];
    alignas(16) float h2p2B[4];
};

__device__ __forceinline__ float sigm(float x)   { return 1.0f / (1.0f + __expf(-x)); }
__device__ __forceinline__ float tanh_f(float x) { return 2.0f / (1.0f + __expf(-2.0f * x)) - 1.0f; }

__device__ __forceinline__ void cpw(float* dst, const float* src, int n, int tid) {
    for (int k = tid; k < n; k += NTHREADS) dst[k] = src[k];
}

} // namespace

__global__ __launch_bounds__(NTHREADS, 1)
void traj_ar_kernel(
    const float* __restrict__ traj_rel,
    const float* __restrict__ obs_pos,
    const float* __restrict__ goal_g,
    const float* __restrict__ embW, const float* __restrict__ embB,
    const float* __restrict__ encWih, const float* __restrict__ encWhh, const float* __restrict__ encB,
    const float* __restrict__ decinW, const float* __restrict__ decinB,
    const float* __restrict__ decWih, const float* __restrict__ decWhh, const float* __restrict__ decB,
    const float* __restrict__ peW, const float* __restrict__ peB,
    const float* __restrict__ W1, const float* __restrict__ b1,
    const float* __restrict__ W2, const float* __restrict__ b2,
    const float* __restrict__ h2p1W, const float* __restrict__ h2p1B,
    const float* __restrict__ h2p2W, const float* __restrict__ h2p2B,
    const int* __restrict__ nei,
    float* __restrict__ out, int out_size)
{
    extern __shared__ unsigned char smem_raw[];
    Smem& sm = *reinterpret_cast<Smem*>(smem_raw);
    const int tid = threadIdx.x;
    const int sb  = blockIdx.x;           // CTA handles samples 2sb, 2sb+1
    const int gb  = sb * NAGC;

    if (sb == 0 && tid == 0) {
        for (int idx = PRED * BTOT * 2; idx < out_size; ++idx) out[idx] = 0.0f;
    }

    // ---------------- weight staging + state init ----------------
    cpw(sm.embW,  embW,  32,  tid);  cpw(sm.embB,  embB,  16, tid);
    cpw(sm.encWih, encWih, 1024, tid); cpw(sm.encWhh, encWhh, 1024, tid); cpw(sm.encB, encB, 64, tid);
    cpw(sm.decinW, decinW, 288, tid);  cpw(sm.decinB, decinB, 16, tid);
    cpw(sm.decWih, decWih, 1024, tid); cpw(sm.decWhh, decWhh, 1024, tid); cpw(sm.decB, decB, 64, tid);
    cpw(sm.peW, peW, 32, tid); cpw(sm.peB, peB, 16, tid);
    for (int idx = tid; idx < 1024; idx += NTHREADS) {
        const int k = idx >> 4, d = idx & 15;
        sm.W1pT[idx] = W1[d * 64 + k];
    }
    cpw(sm.W1h, W1 + 1024, 1024, tid);
    cpw(sm.b1, b1, 64, tid); cpw(sm.W2, W2, 1024, tid); cpw(sm.b2, b2, 16, tid);
    cpw(sm.h2p1W, h2p1W, 288, tid); cpw(sm.h2p1B, h2p1B, 16, tid);
    cpw(sm.h2p2W, h2p2W, 64, tid);  cpw(sm.h2p2B, h2p2B, 4, tid);

    for (int idx = tid; idx < NAGC * 17; idx += NTHREADS) {
        (&sm.h[0][0])[idx] = 0.0f; (&sm.c[0][0])[idx] = 0.0f; (&sm.ctx[0][0])[idx] = 0.0f;
    }
    if (tid < NAGC) {
        sm.nmask[tid] = 0ull;
        const int b = gb + tid;
        const float c0 = obs_pos[((OBS - 1) * BTOT + b) * 2 + 0];
        const float c1 = obs_pos[((OBS - 1) * BTOT + b) * 2 + 1];
        sm.curr[tid][0] = c0; sm.curr[tid][1] = c1;
        sm.outp[tid][0] = traj_rel[((OBS - 1) * BTOT + b) * 2 + 0];
        sm.outp[tid][1] = traj_rel[((OBS - 1) * BTOT + b) * 2 + 1];
        sm.goal[tid][0] = goal_g[b * 2 + 0] - c0;
        sm.goal[tid][1] = goal_g[b * 2 + 1] - c1;
    }
    __syncthreads();
    {   // neighbor masks for both samples: row i (0..127), local j (0..63)
        const int base = gb * NAG;
        for (int flat = tid; flat < NAGC * NAG; flat += NTHREADS) {
            if (nei[base + flat] != 0)
                atomicOr(&sm.nmask[flat >> 6], 1ull << (flat & 63));
        }
    }
    __syncthreads();
    // ---- compacted (i, j_global) pair list, sorted by i ----
    if (tid == 0) {
        int run = 0;
        for (int i = 0; i < NAGC; ++i) { sm.pfx[i] = run; run += __popcll(sm.nmask[i]); }
        sm.pfx[NAGC] = run;
    }
    __syncthreads();
    if (tid < NAGC) {
        unsigned long long m = sm.nmask[tid];
        int w = sm.pfx[tid];
        const int jbase = tid & 64;                // sample offset for j
        const unsigned short ibase = (unsigned short)(tid << 7);
        while (m) {
            const int j = __ffsll((long long)m) - 1;
            m &= m - 1;
            sm.plist[w++] = (unsigned short)(ibase | (unsigned short)(jbase + j));
        }
    }
    __syncthreads();
    const int P       = sm.pfx[NAGC];
    const int pbase   = P / NTHREADS;
    const int prem    = P - pbase * NTHREADS;
    const int mystart = tid * pbase + (tid < prem ? tid : prem);
    const int mycnt   = pbase + (tid < prem ? 1 : 0);

    // LSTM phase layout: 2 threads per agent (tid < 256), 8 gate units each
    const int a2   = tid >> 1;
    const int sub2 = tid & 1;
    const bool lstm_active = (tid < 2 * NAGC);

    // ---------------- history encoder ----------------
    if (lstm_active) {
        for (int t = 0; t < OBS; ++t) {
            const int b = gb + a2;
            const float x0 = traj_rel[(t * BTOT + b) * 2 + 0];
            const float x1 = traj_rel[(t * BTOT + b) * 2 + 1];
            float emb[H];
            #pragma unroll
            for (int u = 0; u < H; ++u)
                emb[u] = fmaxf(fmaf(x0, sm.embW[u], fmaf(x1, sm.embW[16 + u], sm.embB[u])), 0.0f);
            float hold[H];
            #pragma unroll
            for (int d = 0; d < H; ++d) hold[d] = sm.h[a2][d];
            float hn[8], cn[8];
            #pragma unroll
            for (int q = 0; q < 8; ++q) {
                const int u = sub2 * 8 + q;
                float gi = sm.encB[u], gf = sm.encB[16 + u], gg = sm.encB[32 + u], go = sm.encB[48 + u];
                #pragma unroll
                for (int d = 0; d < H; ++d) {
                    const float e = emb[d], hd = hold[d];
                    gi = fmaf(e, sm.encWih[d * 64 + u],        gi); gi = fmaf(hd, sm.encWhh[d * 64 + u],        gi);
                    gf = fmaf(e, sm.encWih[d * 64 + 16 + u],   gf); gf = fmaf(hd, sm.encWhh[d * 64 + 16 + u],   gf);
                    gg = fmaf(e, sm.encWih[d * 64 + 32 + u],   gg); gg = fmaf(hd, sm.encWhh[d * 64 + 32 + u],   gg);
                    go = fmaf(e, sm.encWih[d * 64 + 48 + u],   go); go = fmaf(hd, sm.encWhh[d * 64 + 48 + u],   go);
                }
                const float cN = sigm(gf) * sm.c[a2][u] + sigm(gi) * tanh_f(gg);
                cn[q] = cN; hn[q] = sigm(go) * tanh_f(cN);
            }
            __syncwarp();   // agent thread-pairs are intra-warp
            #pragma unroll
            for (int q = 0; q < 8; ++q) { sm.h[a2][sub2 * 8 + q] = hn[q]; sm.c[a2][sub2 * 8 + q] = cn[q]; }
            __syncwarp();
        }
        #pragma unroll
        for (int q = 0; q < 8; ++q) sm.c[a2][sub2 * 8 + q] = 0.0f;
    }
    __syncthreads();

    // ---------------- autoregressive decoder ----------------
    for (int step = 0; step < PRED; ++step) {
        // decoder input embed + LSTM (2 threads/agent, tid<256)
        if (lstm_active) {
            float ctxv[H];
            #pragma unroll
            for (int d = 0; d < H; ++d) ctxv[d] = sm.ctx[a2][d];
            const float o0 = sm.outp[a2][0], o1 = sm.outp[a2][1];
            float emb[H];
            #pragma unroll
            for (int u = 0; u < H; ++u) {
                float acc = sm.decinB[u];
                #pragma unroll
                for (int d = 0; d < H; ++d) acc = fmaf(ctxv[d], sm.decinW[d * 16 + u], acc);
                acc = fmaf(o0, sm.decinW[256 + u], fmaf(o1, sm.decinW[272 + u], acc));
                emb[u] = fmaxf(acc, 0.0f);
            }
            float hold[H];
            #pragma unroll
            for (int d = 0; d < H; ++d) hold[d] = sm.h[a2][d];
            float hn[8], cn[8];
            #pragma unroll
            for (int q = 0; q < 8; ++q) {
                const int u = sub2 * 8 + q;
                float gi = sm.decB[u], gf = sm.decB[16 + u], gg = sm.decB[32 + u], go = sm.decB[48 + u];
                #pragma unroll
                for (int d = 0; d < H; ++d) {
                    const float e = emb[d], hd = hold[d];
                    gi = fmaf(e, sm.decWih[d * 64 + u],        gi); gi = fmaf(hd, sm.decWhh[d * 64 + u],        gi);
                    gf = fmaf(e, sm.decWih[d * 64 + 16 + u],   gf); gf = fmaf(hd, sm.decWhh[d * 64 + 16 + u],   gf);
                    gg = fmaf(e, sm.decWih[d * 64 + 32 + u],   gg); gg = fmaf(hd, sm.decWhh[d * 64 + 32 + u],   gg);
                    go = fmaf(e, sm.decWih[d * 64 + 48 + u],   go); go = fmaf(hd, sm.decWhh[d * 64 + 48 + u],   go);
                }
                const float cN = sigm(gf) * sm.c[a2][u] + sigm(gi) * tanh_f(gg);
                cn[q] = cN; hn[q] = sigm(go) * tanh_f(cN);
            }
            __syncthreads();   // all reads of old h complete (all threads arrive)
            #pragma unroll
            for (int q = 0; q < 8; ++q) { sm.h[a2][sub2 * 8 + q] = hn[q]; sm.c[a2][sub2 * 8 + q] = cn[q]; }
        } else {
            __syncthreads();
        }
        __syncthreads();

        // hjp[j][k] = h_j . W1h[:,k] + b1[k]  (2 threads/agent, 32 k's each)
        if (lstm_active) {
            const int j = a2, k0 = sub2 * 32;
            float hv[H];
            #pragma unroll
            for (int d = 0; d < H; ++d) hv[d] = sm.h[j][d];
            #pragma unroll
            for (int kk = 0; kk < 32; ++kk) {
                const int k = k0 + kk;
                float acc = sm.b1[k];
                #pragma unroll
                for (int d = 0; d < H; ++d) acc = fmaf(hv[d], sm.W1h[d * 64 + k], acc);
                sm.hjp[j][k] = acc;
            }
        }
        for (int idx = tid; idx < NAGC * 17; idx += NTHREADS) (&sm.ctx[0][0])[idx] = 0.0f;
        __syncthreads();

        // ---- pooling over pair list: tile-1, register segment accumulator ----
        {
            int   cur_i = -1;
            float acc[H];
            for (int t = 0; t < mycnt; ++t) {
                const int pr = sm.plist[mystart + t];
                const int i = pr >> 7, j = pr & 127;
                const float dx = sm.curr[i][0] - sm.curr[j][0];
                const float dy = sm.curr[i][1] - sm.curr[j][1];
                float pe[H], m[H];
                #pragma unroll
                for (int u = 0; u < H; ++u) {
                    pe[u] = fmaxf(fmaf(dx, sm.peW[u], fmaf(dy, sm.peW[16 + u], sm.peB[u])), 0.0f);
                    m[u]  = 0.0f;
                }
                const float* __restrict__ hjrow = sm.hjp[j];
                for (int k = 0; k < 64; ++k) {
                    const float4* w1q = reinterpret_cast<const float4*>(sm.W1pT + (k << 4));
                    const float4 wa = w1q[0], wb = w1q[1], wc = w1q[2], wd = w1q[3];
                    float aA = hjrow[k], aB = 0.0f;   // two independent half-chains
                    aA = fmaf(pe[0],  wa.x, aA); aB = fmaf(pe[8],  wc.x, aB);
                    aA = fmaf(pe[1],  wa.y, aA); aB = fmaf(pe[9],  wc.y, aB);
                    aA = fmaf(pe[2],  wa.z, aA); aB = fmaf(pe[10], wc.z, aB);
                    aA = fmaf(pe[3],  wa.w, aA); aB = fmaf(pe[11], wc.w, aB);
                    aA = fmaf(pe[4],  wb.x, aA); aB = fmaf(pe[12], wd.x, aB);
                    aA = fmaf(pe[5],  wb.y, aA); aB = fmaf(pe[13], wd.y, aB);
                    aA = fmaf(pe[6],  wb.z, aA); aB = fmaf(pe[14], wd.z, aB);
                    aA = fmaf(pe[7],  wb.w, aA); aB = fmaf(pe[15], wd.w, aB);
                    const float av = fmaxf(aA + aB, 0.0f);
                    const float4* w2q = reinterpret_cast<const float4*>(sm.W2 + (k << 4));
                    const float4 va = w2q[0], vb = w2q[1], vc = w2q[2], vd = w2q[3];
                    m[0]  = fmaf(av, va.x, m[0]);  m[1]  = fmaf(av, va.y, m[1]);
                    m[2]  = fmaf(av, va.z, m[2]);  m[3]  = fmaf(av, va.w, m[3]);
                    m[4]  = fmaf(av, vb.x, m[4]);  m[5]  = fmaf(av, vb.y, m[5]);
                    m[6]  = fmaf(av, vb.z, m[6]);  m[7]  = fmaf(av, vb.w, m[7]);
                    m[8]  = fmaf(av, vc.x, m[8]);  m[9]  = fmaf(av, vc.y, m[9]);
                    m[10] = fmaf(av, vc.z, m[10]); m[11] = fmaf(av, vc.w, m[11]);
                    m[12] = fmaf(av, vd.x, m[12]); m[13] = fmaf(av, vd.y, m[13]);
                    m[14] = fmaf(av, vd.z, m[14]); m[15] = fmaf(av, vd.w, m[15]);
                }
                if (i == cur_i) {
                    #pragma unroll
                    for (int u = 0; u < H; ++u) acc[u] += fmaxf(m[u] + sm.b2[u], 0.0f);
                } else {
                    if (cur_i >= 0) {
                        #pragma unroll
                        for (int u = 0; u < H; ++u) atomicAdd(&sm.ctx[cur_i][u], acc[u]);
                    }
                    cur_i = i;
                    #pragma unroll
                    for (int u = 0; u < H; ++u) acc[u] = fmaxf(m[u] + sm.b2[u], 0.0f);
                }
            }
            if (cur_i >= 0) {
                #pragma unroll
                for (int u = 0; u < H; ++u) atomicAdd(&sm.ctx[cur_i][u], acc[u]);
            }
        }
        __syncthreads();

        // output head (one thread per agent, both samples)
        if (tid < NAGC) {
            float hv[H], hh[H];
            #pragma unroll
            for (int u = 0; u < H; ++u) hv[u] = sm.h[tid][u] + sm.ctx[tid][u];
            const float g0 = sm.goal[tid][0], g1 = sm.goal[tid][1];
            #pragma unroll
            for (int u = 0; u < H; ++u) {
                float acc = sm.h2p1B[u];
                #pragma unroll
                for (int d = 0; d < H; ++d) acc = fmaf(hv[d], sm.h2p1W[d * 16 + u], acc);
                acc = fmaf(g0, sm.h2p1W[256 + u], fmaf(g1, sm.h2p1W[272 + u], acc));
                hh[u] = fmaxf(acc, 0.0f);
            }
            float mu0 = sm.h2p2B[0], mu1 = sm.h2p2B[1];
            #pragma unroll
            for (int d = 0; d < H; ++d) {
                mu0 = fmaf(hh[d], sm.h2p2W[d * 4 + 0], mu0);
                mu1 = fmaf(hh[d], sm.h2p2W[d * 4 + 1], mu1);
            }
            const int b = gb + tid;
            out[(step * BTOT + b) * 2 + 0] = mu0;
            out[(step * BTOT + b) * 2 + 1] = mu1;
            sm.outp[tid][0] = mu0; sm.outp[tid][1] = mu1;
            sm.curr[tid][0] += mu0; sm.curr[tid][1] += mu1;
        }
        __syncthreads();
    }
}

extern "C" void kernel_launch(void* const* d_in, const int* in_sizes, int n_in,
                              void* d_out, int out_size)
{
    (void)in_sizes; (void)n_in;
    cudaFuncSetAttribute(traj_ar_kernel, cudaFuncAttributeMaxDynamicSharedMemorySize,
                         (int)sizeof(Smem));
    traj_ar_kernel<<<NCTAS, NTHREADS, sizeof(Smem)>>>(
        (const float*)d_in[0],
        (const float*)d_in[1],
        (const float*)d_in[2],
        (const float*)d_in[4],  (const float*)d_in[5],
        (const float*)d_in[6],  (const float*)d_in[7],  (const float*)d_in[8],
        (const float*)d_in[9],  (const float*)d_in[10],
        (const float*)d_in[11], (const float*)d_in[12], (const float*)d_in[13],
        (const float*)d_in[14], (const float*)d_in[15],
        (const float*)d_in[16], (const float*)d_in[17],
        (const float*)d_in[18], (const float*)d_in[19],
        (const float*)d_in[20], (const float*)d_in[21],
        (const float*)d_in[22], (const float*)d_in[23],
        (const int*)d_in[24],
        (float*)d_out, out_size);
}